// round 1
// baseline (speedup 1.0000x reference)
#include <cuda_runtime.h>
#include <cstdint>

#define SEQ   96
#define PRED  16
#define HID   64
#define FEAT  7
#define BATCH 512
#define BPB   4               // batches per block
#define NBLK  (BATCH/BPB)     // 128 blocks
#define NTHR  256
#define WIN   (SEQ + PRED)    // 112 sliding-window slots

typedef unsigned long long ull;

__device__ __forceinline__ ull pack2(float a, float b){
    ull r; asm("mov.b64 %0, {%1, %2};" : "=l"(r) : "f"(a), "f"(b)); return r;
}
__device__ __forceinline__ void unpack2(ull v, float &a, float &b){
    asm("mov.b64 {%0, %1}, %2;" : "=f"(a), "=f"(b) : "l"(v));
}
// d = a * b + d, packed f32x2 (Blackwell FFMA2) — exact fp32 per lane
__device__ __forceinline__ void ffma2(ull &d, ull a, ull b){
    asm("fma.rn.f32x2 %0, %1, %2, %0;" : "+l"(d) : "l"(a), "l"(b));
}

// Unified activation: s=1 -> sigmoid(x), s=2 -> tanh(x)
//   act = s / (1 + exp(-s*x)) - (s-1)
__device__ __forceinline__ float act(float x, float s, float sm1){
    float e = __expf(-s * x);               // MUFU.EX2 path, ~few ulp
    return __fdividef(s, 1.0f + e) - sm1;   // MUFU.RCP path
}
__device__ __forceinline__ float tanh_fast(float x){
    float e = __expf(-2.0f * x);
    return __fdividef(2.0f, 1.0f + e) - 1.0f;
}

__global__ void __launch_bounds__(NTHR, 1)
lstm_ar_kernel(const float* __restrict__ x,
               const float* __restrict__ W_ih,
               const float* __restrict__ W_hh,
               const float* __restrict__ b_ih,
               const float* __restrict__ b_hh,
               const float* __restrict__ fc_W,
               const float* __restrict__ fc_b,
               float* __restrict__ out)
{
    // window inputs: [idx][feat][b]  (12.5 KB)
    __shared__ float sh_xw[WIN * FEAT * BPB];
    // hidden state: [col][b] so phase-A loads are one broadcast LDS.128
    __shared__ float h_sh[HID * BPB];
    // gate pre/post-activations: [g][j][b]
    __shared__ float sgates[4 * HID * BPB];
    __shared__ float sh_fcW[FEAT * HID];
    __shared__ float sh_fcb[FEAT];

    const int tid = threadIdx.x;          // == gate*64 + j  (phase A identity)
    const int b0  = blockIdx.x * BPB;

    // ---------- one-time init ----------
    for (int i = tid; i < SEQ * FEAT * BPB; i += NTHR){
        int b  = i & 3;
        int r  = i >> 2;
        int kk = r % FEAT;
        int t  = r / FEAT;
        sh_xw[(t * FEAT + kk) * BPB + b] =
            x[(size_t)(b0 + b) * SEQ * FEAT + t * FEAT + kk];
    }
    for (int i = tid; i < FEAT * HID; i += NTHR) sh_fcW[i] = fc_W[i];
    if (tid < FEAT) sh_fcb[tid] = fc_b[tid];
    for (int i = tid; i < HID * BPB; i += NTHR) h_sh[i] = 0.0f;

    // W_hh row for this thread's gate output, pre-splatted to f32x2 (128 regs)
    ull whh2[HID];
    {
        const float4* wr = reinterpret_cast<const float4*>(W_hh + (size_t)tid * HID);
        #pragma unroll
        for (int q = 0; q < HID / 4; q++){
            float4 w = wr[q];
            whh2[4*q+0] = pack2(w.x, w.x);
            whh2[4*q+1] = pack2(w.y, w.y);
            whh2[4*q+2] = pack2(w.z, w.z);
            whh2[4*q+3] = pack2(w.w, w.w);
        }
    }
    ull wih2[FEAT];
    #pragma unroll
    for (int kk = 0; kk < FEAT; kk++){
        float w = W_ih[tid * FEAT + kk];
        wih2[kk] = pack2(w, w);
    }
    const float bias  = b_ih[tid] + b_hh[tid];
    const ull   bias2 = pack2(bias, bias);

    // gate 2 (cell input g) uses tanh; i/f/o use sigmoid — branchless via s
    const float s_act = ((tid >> 6) == 2) ? 2.0f : 1.0f;
    const float s_m1  = s_act - 1.0f;

    // phase-B identity: this thread owns (batch bB, hidden unit jB) cell state
    const int bB = tid & 3;
    const int jB = tid >> 2;
    float c_reg = 0.0f;

    __syncthreads();

    const ulonglong2* hp = reinterpret_cast<const ulonglong2*>(h_sh);

    // ---------- 16 autoregressive iterations × 96 recurrent steps ----------
    for (int k = 0; k < PRED; k++){
        for (int t = 0; t < SEQ; t++){
            const int xidx = k + t;   // index into extended window

            // ---- phase A: gates[tid][b] = act(bias + W_ih.x_t + W_hh.h) ----
            ull acc01 = bias2, acc23 = bias2;
            const ulonglong2* xp =
                reinterpret_cast<const ulonglong2*>(&sh_xw[xidx * FEAT * BPB]);
            #pragma unroll
            for (int kk = 0; kk < FEAT; kk++){
                ulonglong2 xx = xp[kk];            // broadcast LDS.128
                ffma2(acc01, xx.x, wih2[kk]);
                ffma2(acc23, xx.y, wih2[kk]);
            }
            #pragma unroll
            for (int col = 0; col < HID; col++){
                ulonglong2 hh = hp[col];           // broadcast LDS.128
                ffma2(acc01, hh.x, whh2[col]);
                ffma2(acc23, hh.y, whh2[col]);
            }
            float v0, v1, v2, v3;
            unpack2(acc01, v0, v1);
            unpack2(acc23, v2, v3);
            v0 = act(v0, s_act, s_m1);
            v1 = act(v1, s_act, s_m1);
            v2 = act(v2, s_act, s_m1);
            v3 = act(v3, s_act, s_m1);
            *reinterpret_cast<float4*>(&sgates[tid * 4]) = make_float4(v0, v1, v2, v3);
            __syncthreads();

            // ---- phase B: cell update for (bB, jB) ----
            {
                const int off = (jB << 2) + bB;
                float gi = sgates[(0 << 8) + off];
                float gf = sgates[(1 << 8) + off];
                float gg = sgates[(2 << 8) + off];
                float go = sgates[(3 << 8) + off];
                c_reg = gf * c_reg + gi * gg;
                h_sh[off] = go * tanh_fast(c_reg);
            }
            __syncthreads();
        }

        // ---- phase C: pred = h @ fc_W^T + fc_b; append to window; emit ----
        if (tid < FEAT * BPB){
            int b = tid / FEAT;
            int o = tid - b * FEAT;
            float acc = sh_fcb[o];
            #pragma unroll
            for (int j = 0; j < HID; j++)
                acc += h_sh[j * BPB + b] * sh_fcW[o * HID + j];
            out[(size_t)(b0 + b) * PRED * FEAT + k * FEAT + o] = acc;
            sh_xw[((SEQ + k) * FEAT + o) * BPB + b] = acc;
        }
        __syncthreads();
    }
}

extern "C" void kernel_launch(void* const* d_in, const int* in_sizes, int n_in,
                              void* d_out, int out_size)
{
    const float* x    = (const float*)d_in[0];
    const float* W_ih = (const float*)d_in[1];
    const float* W_hh = (const float*)d_in[2];
    const float* b_ih = (const float*)d_in[3];
    const float* b_hh = (const float*)d_in[4];
    const float* fc_W = (const float*)d_in[5];
    const float* fc_b = (const float*)d_in[6];
    float* out = (float*)d_out;

    lstm_ar_kernel<<<NBLK, NTHR>>>(x, W_ih, W_hh, b_ih, b_hh, fc_W, fc_b, out);
}